// round 14
// baseline (speedup 1.0000x reference)
#include <cuda_runtime.h>
#include <stdint.h>

#define NPIX  200704        // 64 * 56 * 56
#define HW    3136          // 56 * 56
#define WID   56
#define NBLKA (NPIX / 256)  // 784 pixel blocks in kA
#define NTHR4 (NPIX / 4)    // kB pixel threads: 50176, 4 px each

// Intermediate: 32 sign bits (channels of h) per pixel, layout [b*HW + s]
__device__ uint32_t g_a[NPIX];

// Prepacked weight records for kB (written by kA's extra block):
//   V/H: uint4{w0,w1,w2,inv_bits} + sh;  P: uint4{w,inv_bits,sh_bits,0}
__device__ uint4 g_wV[96];  __device__ float g_sV[96];
__device__ uint4 g_wH[96];  __device__ float g_sH[96];
__device__ uint4 g_wP[64];

// ---------------------------------------------------------------------------
// Kernel A: x [N=64, C=64, 56, 56] (NCHW) -> g_a sign masks (1 px/thread).
// Block NBLKA is a weight-packing block for kB's tables (hidden under kA).
// ---------------------------------------------------------------------------
__global__ __launch_bounds__(256) void kA(
    const float* __restrict__ x,
    const float* __restrict__ w1, const float* __restrict__ g1,
    const float* __restrict__ b1, const float* __restrict__ m1,
    const float* __restrict__ v1,
    const float* __restrict__ w2, const float* __restrict__ g2,
    const float* __restrict__ b2, const float* __restrict__ m2,
    const float* __restrict__ v2,
    const float* __restrict__ w3, const float* __restrict__ g3,
    const float* __restrict__ b3, const float* __restrict__ m3,
    const float* __restrict__ v3,
    const float* __restrict__ w4, const float* __restrict__ g4,
    const float* __restrict__ b4, const float* __restrict__ m4,
    const float* __restrict__ v4)
{
    const int wrp  = threadIdx.x >> 5;
    const int lane = threadIdx.x & 31;

    if (blockIdx.x == NBLKA) {
        // ---- weight-packing block (uniform branch; runs concurrently)
        for (int o = wrp; o < 96; o += 8) {
            const float* p2 = w2 + (o * 32 + lane) * 3;
            const float* p3 = w3 + (o * 32 + lane) * 3;
            float a0 = p2[0], a1 = p2[1], a2 = p2[2];
            float c0 = p3[0], c1 = p3[1], c2 = p3[2];
            uint32_t x0 = __ballot_sync(0xffffffffu, a0 > 0.0f);
            uint32_t x1 = __ballot_sync(0xffffffffu, a1 > 0.0f);
            uint32_t x2 = __ballot_sync(0xffffffffu, a2 > 0.0f);
            uint32_t y0 = __ballot_sync(0xffffffffu, c0 > 0.0f);
            uint32_t y1 = __ballot_sync(0xffffffffu, c1 > 0.0f);
            uint32_t y2 = __ballot_sync(0xffffffffu, c2 > 0.0f);
            if (lane == 0) {
                float i2 = g2[o] * rsqrtf(v2[o] + 1e-5f);
                g_wV[o] = make_uint4(x0, x1, x2, __float_as_uint(i2));
                g_sV[o] = b2[o] - m2[o] * i2;
                float i3 = g3[o] * rsqrtf(v3[o] + 1e-5f);
                g_wH[o] = make_uint4(y0, y1, y2, __float_as_uint(i3));
                g_sH[o] = b3[o] - m3[o] * i3;
            }
        }
        for (int o = wrp; o < 64; o += 8) {
            uint32_t pb = __ballot_sync(0xffffffffu, w4[o * 32 + lane] > 0.0f);
            if (lane == 0) {
                float i4 = g4[o] * rsqrtf(v4[o] + 1e-5f);
                g_wP[o] = make_uint4(pb, __float_as_uint(i4),
                                     __float_as_uint(b4[o] - m4[o] * i4), 0u);
            }
        }
        return;
    }

    // ---- pixel path
    __shared__ unsigned long long sw1[32];
    __shared__ float sinv[32], ssh[32];

#pragma unroll
    for (int o = wrp; o < 32; o += 8) {
        float lo = w1[o * 64 + lane];
        float hi = w1[o * 64 + 32 + lane];
        uint32_t blo = __ballot_sync(0xffffffffu, lo > 0.0f);
        uint32_t bhi = __ballot_sync(0xffffffffu, hi > 0.0f);
        if (lane == 0)
            sw1[o] = (unsigned long long)blo | ((unsigned long long)bhi << 32);
    }
    if (threadIdx.x < 32) {
        int o = threadIdx.x;
        float inv = g1[o] * rsqrtf(v1[o] + 1e-5f);
        sinv[o] = inv;
        ssh[o]  = b1[o] - m1[o] * inv;
    }
    __syncthreads();

    int p = blockIdx.x * 256 + threadIdx.x;   // global pixel index = b*HW + s
    int b = p / HW;
    int s = p - b * HW;
    const float* xb = x + (size_t)b * 64 * HW + s;

    // 4 independent 16-bit accumulator chains (ILP), merged at the end.
    uint32_t acc0 = 0, acc1 = 0, acc2 = 0, acc3 = 0;
#pragma unroll
    for (int c = 0; c < 16; c++) {
        if (__ldcs(xb + (size_t)c * HW) > 0.0f)        acc0 |= 1u << c;
        if (__ldcs(xb + (size_t)(c + 16) * HW) > 0.0f) acc1 |= 1u << c;
        if (__ldcs(xb + (size_t)(c + 32) * HW) > 0.0f) acc2 |= 1u << c;
        if (__ldcs(xb + (size_t)(c + 48) * HW) > 0.0f) acc3 |= 1u << c;
    }
    unsigned long long xbits =
        (unsigned long long)(acc0 | (acc1 << 16)) |
        ((unsigned long long)(acc2 | (acc3 << 16)) << 32);

    uint32_t alo = 0, ahi = 0;
#pragma unroll
    for (int o = 0; o < 16; o++) {
        {
            int d = 64 - 2 * __popcll(xbits ^ sw1[o]);
            if (fmaf((float)d, sinv[o], ssh[o]) > 0.0f) alo |= 1u << o;
        }
        {
            int o2 = o + 16;
            int d = 64 - 2 * __popcll(xbits ^ sw1[o2]);
            if (fmaf((float)d, sinv[o2], ssh[o2]) > 0.0f) ahi |= 1u << o;
        }
    }
    g_a[p] = alo | (ahi << 16);
}

// ---------------------------------------------------------------------------
// Kernel B: g_a -> output [64,256,56,56]. Grid (196, 8); 4 px/thread.
// Weight tables prepacked in global (L2-hot) -> no smem, no barrier.
// FMA-pipe rebalance: rv = fma(Sf, 2*inv, fma(pvf, -inv, sh)).
// ---------------------------------------------------------------------------
__global__ __launch_bounds__(256) void kB(float* __restrict__ out)
{
    const int grp = blockIdx.y;        // 0..7

    const int q  = blockIdx.x * 256 + threadIdx.x;  // 0..50175
    const int p  = q * 4;
    const int bb = p / HW;
    const int s  = p - bb * HW;          // multiple of 4
    const int y  = s / WID;
    const int xs = s - y * WID;          // 0..52, multiple of 4

    uint4 C = *(const uint4*)&g_a[p];
    int pc0 = __popc(C.x), pc1 = __popc(C.y), pc2 = __popc(C.z), pc3 = __popc(C.w);
    float* ob = out + (size_t)bb * 256 * HW + s;

    if (grp < 3) {
        // ---- Branch V: 3x1 vertical conv
        uint4 U = make_uint4(0, 0, 0, 0), D = make_uint4(0, 0, 0, 0);
        if (y > 0)  U = *(const uint4*)&g_a[p - WID];
        if (y < 55) D = *(const uint4*)&g_a[p + WID];
        float pv0 = (float)(__popc(U.x) + pc0 + __popc(D.x));
        float pv1 = (float)(__popc(U.y) + pc1 + __popc(D.y));
        float pv2 = (float)(__popc(U.z) + pc2 + __popc(D.z));
        float pv3 = (float)(__popc(U.w) + pc3 + __popc(D.w));

        const uint4*  wt = g_wV + grp * 32;
        const float*  st = g_sV + grp * 32;
        float* o1 = ob + (size_t)(grp * 32) * HW;
#pragma unroll 8
        for (int o = 0; o < 32; o++) {
            uint4 wv = __ldg(&wt[o]);
            float inv = __uint_as_float(wv.w);
            float sh  = __ldg(&st[o]);
            float inv2 = inv + inv;
            float4 rv;
            int S;
            S = __popc(U.x & wv.x) + __popc(C.x & wv.y) + __popc(D.x & wv.z);
            rv.x = fmaxf(fmaf((float)S, inv2, fmaf(pv0, -inv, sh)), 0.0f);
            S = __popc(U.y & wv.x) + __popc(C.y & wv.y) + __popc(D.y & wv.z);
            rv.y = fmaxf(fmaf((float)S, inv2, fmaf(pv1, -inv, sh)), 0.0f);
            S = __popc(U.z & wv.x) + __popc(C.z & wv.y) + __popc(D.z & wv.z);
            rv.z = fmaxf(fmaf((float)S, inv2, fmaf(pv2, -inv, sh)), 0.0f);
            S = __popc(U.w & wv.x) + __popc(C.w & wv.y) + __popc(D.w & wv.z);
            rv.w = fmaxf(fmaf((float)S, inv2, fmaf(pv3, -inv, sh)), 0.0f);
            __stcs((float4*)(o1 + (size_t)o * HW), rv);
        }
    } else if (grp < 6) {
        // ---- Branch H: 1x3 horizontal conv
        uint32_t hL = (xs > 0)  ? g_a[p - 1] : 0u;
        uint32_t hR = (xs < 52) ? g_a[p + 4] : 0u;
        float ph0 = (float)(__popc(hL) + pc0 + pc1);
        float ph1 = (float)(pc0 + pc1 + pc2);
        float ph2 = (float)(pc1 + pc2 + pc3);
        float ph3 = (float)(pc2 + pc3 + __popc(hR));

        const uint4* wt = g_wH + (grp - 3) * 32;
        const float* st = g_sH + (grp - 3) * 32;
        float* o2 = ob + (size_t)(96 + (grp - 3) * 32) * HW;
#pragma unroll 8
        for (int o = 0; o < 32; o++) {
            uint4 wv = __ldg(&wt[o]);
            float inv = __uint_as_float(wv.w);
            float sh  = __ldg(&st[o]);
            float inv2 = inv + inv;
            float4 rv;
            int S;
            S = __popc(hL  & wv.x) + __popc(C.x & wv.y) + __popc(C.y & wv.z);
            rv.x = fmaxf(fmaf((float)S, inv2, fmaf(ph0, -inv, sh)), 0.0f);
            S = __popc(C.x & wv.x) + __popc(C.y & wv.y) + __popc(C.z & wv.z);
            rv.y = fmaxf(fmaf((float)S, inv2, fmaf(ph1, -inv, sh)), 0.0f);
            S = __popc(C.y & wv.x) + __popc(C.z & wv.y) + __popc(C.w & wv.z);
            rv.z = fmaxf(fmaf((float)S, inv2, fmaf(ph2, -inv, sh)), 0.0f);
            S = __popc(C.z & wv.x) + __popc(C.w & wv.y) + __popc(hR  & wv.z);
            rv.w = fmaxf(fmaf((float)S, inv2, fmaf(ph3, -inv, sh)), 0.0f);
            __stcs((float4*)(o2 + (size_t)o * HW), rv);
        }
    } else {
        // ---- Branch P: 1x1 conv
        float pf0 = (float)pc0, pf1 = (float)pc1, pf2 = (float)pc2, pf3 = (float)pc3;
        const uint4* wt = g_wP + (grp - 6) * 32;
        float* o3 = ob + (size_t)(192 + (grp - 6) * 32) * HW;
#pragma unroll 8
        for (int o = 0; o < 32; o++) {
            uint4 wv = __ldg(&wt[o]);
            float inv = __uint_as_float(wv.y);
            float sh  = __uint_as_float(wv.z);
            float inv2 = inv + inv;
            float4 rv;
            rv.x = fmaxf(fmaf((float)__popc(C.x & wv.x), inv2, fmaf(pf0, -inv, sh)), 0.0f);
            rv.y = fmaxf(fmaf((float)__popc(C.y & wv.x), inv2, fmaf(pf1, -inv, sh)), 0.0f);
            rv.z = fmaxf(fmaf((float)__popc(C.z & wv.x), inv2, fmaf(pf2, -inv, sh)), 0.0f);
            rv.w = fmaxf(fmaf((float)__popc(C.w & wv.x), inv2, fmaf(pf3, -inv, sh)), 0.0f);
            __stcs((float4*)(o3 + (size_t)o * HW), rv);
        }
    }
}

// ---------------------------------------------------------------------------
extern "C" void kernel_launch(void* const* d_in, const int* in_sizes, int n_in,
                              void* d_out, int out_size)
{
    const float* x = (const float*)d_in[0];
    kA<<<NBLKA + 1, 256>>>(x,
        (const float*)d_in[1],  (const float*)d_in[2],
        (const float*)d_in[3],  (const float*)d_in[4],
        (const float*)d_in[5],
        (const float*)d_in[6],  (const float*)d_in[7],
        (const float*)d_in[8],  (const float*)d_in[9],
        (const float*)d_in[10],
        (const float*)d_in[11], (const float*)d_in[12],
        (const float*)d_in[13], (const float*)d_in[14],
        (const float*)d_in[15],
        (const float*)d_in[16], (const float*)d_in[17],
        (const float*)d_in[18], (const float*)d_in[19],
        (const float*)d_in[20]);
    dim3 gridB(NTHR4 / 256, 8);
    kB<<<gridB, 256>>>((float*)d_out);
}

// round 15
// speedup vs baseline: 1.1166x; 1.1166x over previous
#include <cuda_runtime.h>
#include <stdint.h>

#define NPIX  200704        // 64 * 56 * 56
#define HW    3136          // 56 * 56
#define WID   56
#define NTHR4 (NPIX / 4)    // kB pixel threads: 50176, 4 px each

// Intermediate: 32 sign bits (channels of h) per pixel, layout [b*HW + s]
__device__ uint32_t g_a[NPIX];

// ---------------------------------------------------------------------------
// Kernel A: x [N=64, C=64, 56, 56] (NCHW) -> g_a sign masks.
// 1 px/thread, 784 blocks. Independent accumulator chains; streaming loads.
// ---------------------------------------------------------------------------
__global__ __launch_bounds__(256) void kA(const float* __restrict__ x,
                                          const float* __restrict__ w1,
                                          const float* __restrict__ g1,
                                          const float* __restrict__ b1,
                                          const float* __restrict__ m1,
                                          const float* __restrict__ v1)
{
    __shared__ unsigned long long sw1[32];
    __shared__ float sinv[32], ssh[32];

    const int wrp  = threadIdx.x >> 5;
    const int lane = threadIdx.x & 31;

#pragma unroll
    for (int o = wrp; o < 32; o += 8) {
        float lo = w1[o * 64 + lane];
        float hi = w1[o * 64 + 32 + lane];
        uint32_t blo = __ballot_sync(0xffffffffu, lo > 0.0f);
        uint32_t bhi = __ballot_sync(0xffffffffu, hi > 0.0f);
        if (lane == 0)
            sw1[o] = (unsigned long long)blo | ((unsigned long long)bhi << 32);
    }
    if (threadIdx.x < 32) {
        int o = threadIdx.x;
        float inv = g1[o] * rsqrtf(v1[o] + 1e-5f);
        sinv[o] = inv;
        ssh[o]  = b1[o] - m1[o] * inv;
    }
    __syncthreads();

    int p = blockIdx.x * 256 + threadIdx.x;   // global pixel index = b*HW + s
    if (p >= NPIX) return;
    int b = p / HW;
    int s = p - b * HW;
    const float* xb = x + (size_t)b * 64 * HW + s;

    // 4 independent 16-bit accumulator chains (ILP), merged at the end.
    uint32_t acc0 = 0, acc1 = 0, acc2 = 0, acc3 = 0;
#pragma unroll
    for (int c = 0; c < 16; c++) {
        if (__ldcs(xb + (size_t)c * HW) > 0.0f)        acc0 |= 1u << c;
        if (__ldcs(xb + (size_t)(c + 16) * HW) > 0.0f) acc1 |= 1u << c;
        if (__ldcs(xb + (size_t)(c + 32) * HW) > 0.0f) acc2 |= 1u << c;
        if (__ldcs(xb + (size_t)(c + 48) * HW) > 0.0f) acc3 |= 1u << c;
    }
    unsigned long long xbits =
        (unsigned long long)(acc0 | (acc1 << 16)) |
        ((unsigned long long)(acc2 | (acc3 << 16)) << 32);

    uint32_t alo = 0, ahi = 0;
#pragma unroll
    for (int o = 0; o < 16; o++) {
        {
            int d = 64 - 2 * __popcll(xbits ^ sw1[o]);
            if (fmaf((float)d, sinv[o], ssh[o]) > 0.0f) alo |= 1u << o;
        }
        {
            int o2 = o + 16;
            int d = 64 - 2 * __popcll(xbits ^ sw1[o2]);
            if (fmaf((float)d, sinv[o2], ssh[o2]) > 0.0f) ahi |= 1u << o;
        }
    }
    g_a[p] = alo | (ahi << 16);
}

// ---------------------------------------------------------------------------
// Kernel B: g_a -> output [64,256,56,56].
// Grid (196, 8): blockIdx.x = pixel tile (256 threads x 4 px),
// blockIdx.y = 32-channel group: 0-2 = V (w2), 3-5 = H (w3), 6-7 = P (w4).
// smem ballot prologue (32 ch) + FMA-pipe rebalance + streaming stores.
// ---------------------------------------------------------------------------
__global__ __launch_bounds__(256) void kB(
    const float* __restrict__ w2, const float* __restrict__ g2,
    const float* __restrict__ b2, const float* __restrict__ m2,
    const float* __restrict__ v2,
    const float* __restrict__ w3, const float* __restrict__ g3,
    const float* __restrict__ b3, const float* __restrict__ m3,
    const float* __restrict__ v3,
    const float* __restrict__ w4, const float* __restrict__ g4,
    const float* __restrict__ b4, const float* __restrict__ m4,
    const float* __restrict__ v4,
    float* __restrict__ out)
{
    __shared__ __align__(16) uint32_t sw[32 * 4];
    __shared__ float ssh[32];

    const int grp  = blockIdx.y;        // 0..7
    const int wrp  = threadIdx.x >> 5;  // 0..7
    const int lane = threadIdx.x & 31;

    // ---- pixel indices + hoisted g_a loads (independent of prep)
    const int q  = blockIdx.x * 256 + threadIdx.x;  // 0..50175
    const int p  = q * 4;
    const int bb = p / HW;
    const int s  = p - bb * HW;          // multiple of 4
    const int y  = s / WID;
    const int xs = s - y * WID;          // 0..52, multiple of 4

    uint4 C = *(const uint4*)&g_a[p];
    uint4 U = make_uint4(0, 0, 0, 0), D = make_uint4(0, 0, 0, 0);
    uint32_t hL = 0u, hR = 0u;
    if (grp < 3) {
        if (y > 0)  U = *(const uint4*)&g_a[p - WID];
        if (y < 55) D = *(const uint4*)&g_a[p + WID];
    } else if (grp < 6) {
        hL = (xs > 0)  ? g_a[p - 1] : 0u;
        hR = (xs < 52) ? g_a[p + 4] : 0u;
    }

    // ---- per-block prep: 32 channels only (overlaps the loads above)
    if (grp < 6) {
        const float* wsrc = (grp < 3) ? w2 : w3;
        const int base = (grp < 3 ? grp : grp - 3) * 32;
#pragma unroll
        for (int o = wrp; o < 32; o += 8) {
            const float* pw = wsrc + ((base + o) * 32 + lane) * 3;
            float a0 = pw[0], a1 = pw[1], a2 = pw[2];
            uint32_t x0 = __ballot_sync(0xffffffffu, a0 > 0.0f);
            uint32_t x1 = __ballot_sync(0xffffffffu, a1 > 0.0f);
            uint32_t x2 = __ballot_sync(0xffffffffu, a2 > 0.0f);
            if (lane == 0) {
                sw[4 * o] = x0; sw[4 * o + 1] = x1; sw[4 * o + 2] = x2;
            }
        }
        if (threadIdx.x < 32) {
            int c = base + threadIdx.x;
            float inv, sh;
            if (grp < 3) {
                inv = g2[c] * rsqrtf(v2[c] + 1e-5f);
                sh  = b2[c] - m2[c] * inv;
            } else {
                inv = g3[c] * rsqrtf(v3[c] + 1e-5f);
                sh  = b3[c] - m3[c] * inv;
            }
            sw[4 * threadIdx.x + 3] = __float_as_uint(inv);
            ssh[threadIdx.x] = sh;
        }
    } else {
        const int base = (grp - 6) * 32;
#pragma unroll
        for (int o = wrp; o < 32; o += 8) {
            uint32_t pb = __ballot_sync(0xffffffffu, w4[(base + o) * 32 + lane] > 0.0f);
            if (lane == 0) sw[4 * o] = pb;
        }
        if (threadIdx.x < 32) {
            int c = base + threadIdx.x;
            float inv = g4[c] * rsqrtf(v4[c] + 1e-5f);
            sw[4 * threadIdx.x + 1] = __float_as_uint(inv);
            sw[4 * threadIdx.x + 2] = __float_as_uint(b4[c] - m4[c] * inv);
        }
    }
    __syncthreads();

    int pc0 = __popc(C.x), pc1 = __popc(C.y), pc2 = __popc(C.z), pc3 = __popc(C.w);
    float* ob = out + (size_t)bb * 256 * HW + s;

    if (grp < 3) {
        // ---- Branch V: 3x1 vertical conv
        float pv0 = (float)(__popc(U.x) + pc0 + __popc(D.x));
        float pv1 = (float)(__popc(U.y) + pc1 + __popc(D.y));
        float pv2 = (float)(__popc(U.z) + pc2 + __popc(D.z));
        float pv3 = (float)(__popc(U.w) + pc3 + __popc(D.w));

        float* o1 = ob + (size_t)(grp * 32) * HW;
#pragma unroll 8
        for (int o = 0; o < 32; o++) {
            uint4 wv = *(const uint4*)&sw[4 * o];
            float inv = __uint_as_float(wv.w);
            float sh  = ssh[o];
            float inv2 = inv + inv;
            float4 rv;
            int S;
            S = __popc(U.x & wv.x) + __popc(C.x & wv.y) + __popc(D.x & wv.z);
            rv.x = fmaxf(fmaf((float)S, inv2, fmaf(pv0, -inv, sh)), 0.0f);
            S = __popc(U.y & wv.x) + __popc(C.y & wv.y) + __popc(D.y & wv.z);
            rv.y = fmaxf(fmaf((float)S, inv2, fmaf(pv1, -inv, sh)), 0.0f);
            S = __popc(U.z & wv.x) + __popc(C.z & wv.y) + __popc(D.z & wv.z);
            rv.z = fmaxf(fmaf((float)S, inv2, fmaf(pv2, -inv, sh)), 0.0f);
            S = __popc(U.w & wv.x) + __popc(C.w & wv.y) + __popc(D.w & wv.z);
            rv.w = fmaxf(fmaf((float)S, inv2, fmaf(pv3, -inv, sh)), 0.0f);
            __stcs((float4*)(o1 + (size_t)o * HW), rv);
        }
    } else if (grp < 6) {
        // ---- Branch H: 1x3 horizontal conv
        float ph0 = (float)(__popc(hL) + pc0 + pc1);
        float ph1 = (float)(pc0 + pc1 + pc2);
        float ph2 = (float)(pc1 + pc2 + pc3);
        float ph3 = (float)(pc2 + pc3 + __popc(hR));

        float* o2 = ob + (size_t)(96 + (grp - 3) * 32) * HW;
#pragma unroll 8
        for (int o = 0; o < 32; o++) {
            uint4 wv = *(const uint4*)&sw[4 * o];
            float inv = __uint_as_float(wv.w);
            float sh  = ssh[o];
            float inv2 = inv + inv;
            float4 rv;
            int S;
            S = __popc(hL  & wv.x) + __popc(C.x & wv.y) + __popc(C.y & wv.z);
            rv.x = fmaxf(fmaf((float)S, inv2, fmaf(ph0, -inv, sh)), 0.0f);
            S = __popc(C.x & wv.x) + __popc(C.y & wv.y) + __popc(C.z & wv.z);
            rv.y = fmaxf(fmaf((float)S, inv2, fmaf(ph1, -inv, sh)), 0.0f);
            S = __popc(C.y & wv.x) + __popc(C.z & wv.y) + __popc(C.w & wv.z);
            rv.z = fmaxf(fmaf((float)S, inv2, fmaf(ph2, -inv, sh)), 0.0f);
            S = __popc(C.z & wv.x) + __popc(C.w & wv.y) + __popc(hR  & wv.z);
            rv.w = fmaxf(fmaf((float)S, inv2, fmaf(ph3, -inv, sh)), 0.0f);
            __stcs((float4*)(o2 + (size_t)o * HW), rv);
        }
    } else {
        // ---- Branch P: 1x1 conv (inv in slot 1, sh in slot 2)
        float pf0 = (float)pc0, pf1 = (float)pc1, pf2 = (float)pc2, pf3 = (float)pc3;
        float* o3 = ob + (size_t)(192 + (grp - 6) * 32) * HW;
#pragma unroll 8
        for (int o = 0; o < 32; o++) {
            uint4 wv = *(const uint4*)&sw[4 * o];
            float inv = __uint_as_float(wv.y);
            float sh  = __uint_as_float(wv.z);
            float inv2 = inv + inv;
            float4 rv;
            rv.x = fmaxf(fmaf((float)__popc(C.x & wv.x), inv2, fmaf(pf0, -inv, sh)), 0.0f);
            rv.y = fmaxf(fmaf((float)__popc(C.y & wv.x), inv2, fmaf(pf1, -inv, sh)), 0.0f);
            rv.z = fmaxf(fmaf((float)__popc(C.z & wv.x), inv2, fmaf(pf2, -inv, sh)), 0.0f);
            rv.w = fmaxf(fmaf((float)__popc(C.w & wv.x), inv2, fmaf(pf3, -inv, sh)), 0.0f);
            __stcs((float4*)(o3 + (size_t)o * HW), rv);
        }
    }
}

// ---------------------------------------------------------------------------
extern "C" void kernel_launch(void* const* d_in, const int* in_sizes, int n_in,
                              void* d_out, int out_size)
{
    const float* x = (const float*)d_in[0];
    kA<<<NPIX / 256, 256>>>(x,
                            (const float*)d_in[1], (const float*)d_in[2],
                            (const float*)d_in[3], (const float*)d_in[4],
                            (const float*)d_in[5]);
    dim3 gridB(NTHR4 / 256, 8);
    kB<<<gridB, 256>>>(
        (const float*)d_in[6],  (const float*)d_in[7],
        (const float*)d_in[8],  (const float*)d_in[9],
        (const float*)d_in[10],
        (const float*)d_in[11], (const float*)d_in[12],
        (const float*)d_in[13], (const float*)d_in[14],
        (const float*)d_in[15],
        (const float*)d_in[16], (const float*)d_in[17],
        (const float*)d_in[18], (const float*)d_in[19],
        (const float*)d_in[20],
        (float*)d_out);
}

// round 16
// speedup vs baseline: 1.1173x; 1.0006x over previous
#include <cuda_runtime.h>
#include <stdint.h>

#define NPIX  200704        // 64 * 56 * 56
#define HW    3136          // 56 * 56
#define WID   56
#define NTHR4 (NPIX / 4)    // kB pixel threads: 50176, 4 px each

// Intermediate: 32 sign bits (channels of h) per pixel, layout [b*HW + s]
__device__ uint32_t g_a[NPIX];

// ---------------------------------------------------------------------------
// Kernel A: x [N=64, C=64, 56, 56] (NCHW) -> g_a sign masks.
// 1 px/thread, 784 blocks. Integer-threshold binarization: per channel the
// monotonic predicate fmaf(64-2*pc, inv, sh) > 0 is collapsed at prep time
// to  a*pc + b <= 0  (exact over the full pc domain -> bit-identical output).
// ---------------------------------------------------------------------------
__global__ __launch_bounds__(256) void kA(const float* __restrict__ x,
                                          const float* __restrict__ w1,
                                          const float* __restrict__ g1,
                                          const float* __restrict__ b1,
                                          const float* __restrict__ m1,
                                          const float* __restrict__ v1)
{
    __shared__ unsigned long long sw1[32];
    __shared__ int sA[32], sB[32];

    const int wrp  = threadIdx.x >> 5;
    const int lane = threadIdx.x & 31;

#pragma unroll
    for (int o = wrp; o < 32; o += 8) {
        float lo = w1[o * 64 + lane];
        float hi = w1[o * 64 + 32 + lane];
        uint32_t blo = __ballot_sync(0xffffffffu, lo > 0.0f);
        uint32_t bhi = __ballot_sync(0xffffffffu, hi > 0.0f);
        if (lane == 0)
            sw1[o] = (unsigned long long)blo | ((unsigned long long)bhi << 32);
    }
    if (threadIdx.x < 32) {
        int o = threadIdx.x;
        float inv = g1[o] * rsqrtf(v1[o] + 1e-5f);
        float sh  = b1[o] - m1[o] * inv;
        int a, b;
        if (inv > 0.0f) {
            // f(pc) decreasing: true set is a prefix {0..T}; bit <=> pc - T <= 0
            int T = -1;
            for (int pc = 0; pc <= 64; pc++)
                if (fmaf((float)(64 - 2 * pc), inv, sh) > 0.0f) T = pc;
            a = 1; b = -T;
        } else if (inv < 0.0f) {
            // f(pc) increasing: true set is a suffix {T..64}; bit <=> T - pc <= 0
            int T = 65;
            for (int pc = 64; pc >= 0; pc--)
                if (fmaf((float)(64 - 2 * pc), inv, sh) > 0.0f) T = pc;
            a = -1; b = T;
        } else {
            // constant predicate
            a = 0; b = (sh > 0.0f) ? -1 : 1;   // b<=0 ? always-true : always-false
        }
        sA[o] = a; sB[o] = b;
    }
    __syncthreads();

    int p = blockIdx.x * 256 + threadIdx.x;   // global pixel index = b*HW + s
    if (p >= NPIX) return;
    int b = p / HW;
    int s = p - b * HW;
    const float* xb = x + (size_t)b * 64 * HW + s;

    // 4 independent 16-bit accumulator chains (ILP), merged at the end.
    uint32_t acc0 = 0, acc1 = 0, acc2 = 0, acc3 = 0;
#pragma unroll
    for (int c = 0; c < 16; c++) {
        if (__ldcs(xb + (size_t)c * HW) > 0.0f)        acc0 |= 1u << c;
        if (__ldcs(xb + (size_t)(c + 16) * HW) > 0.0f) acc1 |= 1u << c;
        if (__ldcs(xb + (size_t)(c + 32) * HW) > 0.0f) acc2 |= 1u << c;
        if (__ldcs(xb + (size_t)(c + 48) * HW) > 0.0f) acc3 |= 1u << c;
    }
    unsigned long long xbits =
        (unsigned long long)(acc0 | (acc1 << 16)) |
        ((unsigned long long)(acc2 | (acc3 << 16)) << 32);

    // 2 independent output-bit chains; pure-integer threshold test.
    uint32_t alo = 0, ahi = 0;
#pragma unroll
    for (int o = 0; o < 16; o++) {
        {
            int pc = __popcll(xbits ^ sw1[o]);
            if (sA[o] * pc + sB[o] <= 0) alo |= 1u << o;
        }
        {
            int o2 = o + 16;
            int pc = __popcll(xbits ^ sw1[o2]);
            if (sA[o2] * pc + sB[o2] <= 0) ahi |= 1u << o;
        }
    }
    g_a[p] = alo | (ahi << 16);
}

// ---------------------------------------------------------------------------
// Kernel B: g_a -> output [64,256,56,56].
// Grid (196, 8): blockIdx.x = pixel tile (256 threads x 4 px),
// blockIdx.y = 32-channel group: 0-2 = V (w2), 3-5 = H (w3), 6-7 = P (w4).
// smem ballot prologue (32 ch) + FMA-pipe rebalance + streaming stores.
// ---------------------------------------------------------------------------
__global__ __launch_bounds__(256) void kB(
    const float* __restrict__ w2, const float* __restrict__ g2,
    const float* __restrict__ b2, const float* __restrict__ m2,
    const float* __restrict__ v2,
    const float* __restrict__ w3, const float* __restrict__ g3,
    const float* __restrict__ b3, const float* __restrict__ m3,
    const float* __restrict__ v3,
    const float* __restrict__ w4, const float* __restrict__ g4,
    const float* __restrict__ b4, const float* __restrict__ m4,
    const float* __restrict__ v4,
    float* __restrict__ out)
{
    __shared__ __align__(16) uint32_t sw[32 * 4];
    __shared__ float ssh[32];

    const int grp  = blockIdx.y;        // 0..7
    const int wrp  = threadIdx.x >> 5;  // 0..7
    const int lane = threadIdx.x & 31;

    // ---- pixel indices + hoisted g_a loads (independent of prep)
    const int q  = blockIdx.x * 256 + threadIdx.x;  // 0..50175
    const int p  = q * 4;
    const int bb = p / HW;
    const int s  = p - bb * HW;          // multiple of 4
    const int y  = s / WID;
    const int xs = s - y * WID;          // 0..52, multiple of 4

    uint4 C = *(const uint4*)&g_a[p];
    uint4 U = make_uint4(0, 0, 0, 0), D = make_uint4(0, 0, 0, 0);
    uint32_t hL = 0u, hR = 0u;
    if (grp < 3) {
        if (y > 0)  U = *(const uint4*)&g_a[p - WID];
        if (y < 55) D = *(const uint4*)&g_a[p + WID];
    } else if (grp < 6) {
        hL = (xs > 0)  ? g_a[p - 1] : 0u;
        hR = (xs < 52) ? g_a[p + 4] : 0u;
    }

    // ---- per-block prep: 32 channels only (overlaps the loads above)
    if (grp < 6) {
        const float* wsrc = (grp < 3) ? w2 : w3;
        const int base = (grp < 3 ? grp : grp - 3) * 32;
#pragma unroll
        for (int o = wrp; o < 32; o += 8) {
            const float* pw = wsrc + ((base + o) * 32 + lane) * 3;
            float a0 = pw[0], a1 = pw[1], a2 = pw[2];
            uint32_t x0 = __ballot_sync(0xffffffffu, a0 > 0.0f);
            uint32_t x1 = __ballot_sync(0xffffffffu, a1 > 0.0f);
            uint32_t x2 = __ballot_sync(0xffffffffu, a2 > 0.0f);
            if (lane == 0) {
                sw[4 * o] = x0; sw[4 * o + 1] = x1; sw[4 * o + 2] = x2;
            }
        }
        if (threadIdx.x < 32) {
            int c = base + threadIdx.x;
            float inv, sh;
            if (grp < 3) {
                inv = g2[c] * rsqrtf(v2[c] + 1e-5f);
                sh  = b2[c] - m2[c] * inv;
            } else {
                inv = g3[c] * rsqrtf(v3[c] + 1e-5f);
                sh  = b3[c] - m3[c] * inv;
            }
            sw[4 * threadIdx.x + 3] = __float_as_uint(inv);
            ssh[threadIdx.x] = sh;
        }
    } else {
        const int base = (grp - 6) * 32;
#pragma unroll
        for (int o = wrp; o < 32; o += 8) {
            uint32_t pb = __ballot_sync(0xffffffffu, w4[(base + o) * 32 + lane] > 0.0f);
            if (lane == 0) sw[4 * o] = pb;
        }
        if (threadIdx.x < 32) {
            int c = base + threadIdx.x;
            float inv = g4[c] * rsqrtf(v4[c] + 1e-5f);
            sw[4 * threadIdx.x + 1] = __float_as_uint(inv);
            sw[4 * threadIdx.x + 2] = __float_as_uint(b4[c] - m4[c] * inv);
        }
    }
    __syncthreads();

    int pc0 = __popc(C.x), pc1 = __popc(C.y), pc2 = __popc(C.z), pc3 = __popc(C.w);
    float* ob = out + (size_t)bb * 256 * HW + s;

    if (grp < 3) {
        // ---- Branch V: 3x1 vertical conv
        float pv0 = (float)(__popc(U.x) + pc0 + __popc(D.x));
        float pv1 = (float)(__popc(U.y) + pc1 + __popc(D.y));
        float pv2 = (float)(__popc(U.z) + pc2 + __popc(D.z));
        float pv3 = (float)(__popc(U.w) + pc3 + __popc(D.w));

        float* o1 = ob + (size_t)(grp * 32) * HW;
#pragma unroll 8
        for (int o = 0; o < 32; o++) {
            uint4 wv = *(const uint4*)&sw[4 * o];
            float inv = __uint_as_float(wv.w);
            float sh  = ssh[o];
            float inv2 = inv + inv;
            float4 rv;
            int S;
            S = __popc(U.x & wv.x) + __popc(C.x & wv.y) + __popc(D.x & wv.z);
            rv.x = fmaxf(fmaf((float)S, inv2, fmaf(pv0, -inv, sh)), 0.0f);
            S = __popc(U.y & wv.x) + __popc(C.y & wv.y) + __popc(D.y & wv.z);
            rv.y = fmaxf(fmaf((float)S, inv2, fmaf(pv1, -inv, sh)), 0.0f);
            S = __popc(U.z & wv.x) + __popc(C.z & wv.y) + __popc(D.z & wv.z);
            rv.z = fmaxf(fmaf((float)S, inv2, fmaf(pv2, -inv, sh)), 0.0f);
            S = __popc(U.w & wv.x) + __popc(C.w & wv.y) + __popc(D.w & wv.z);
            rv.w = fmaxf(fmaf((float)S, inv2, fmaf(pv3, -inv, sh)), 0.0f);
            __stcs((float4*)(o1 + (size_t)o * HW), rv);
        }
    } else if (grp < 6) {
        // ---- Branch H: 1x3 horizontal conv
        float ph0 = (float)(__popc(hL) + pc0 + pc1);
        float ph1 = (float)(pc0 + pc1 + pc2);
        float ph2 = (float)(pc1 + pc2 + pc3);
        float ph3 = (float)(pc2 + pc3 + __popc(hR));

        float* o2 = ob + (size_t)(96 + (grp - 3) * 32) * HW;
#pragma unroll 8
        for (int o = 0; o < 32; o++) {
            uint4 wv = *(const uint4*)&sw[4 * o];
            float inv = __uint_as_float(wv.w);
            float sh  = ssh[o];
            float inv2 = inv + inv;
            float4 rv;
            int S;
            S = __popc(hL  & wv.x) + __popc(C.x & wv.y) + __popc(C.y & wv.z);
            rv.x = fmaxf(fmaf((float)S, inv2, fmaf(ph0, -inv, sh)), 0.0f);
            S = __popc(C.x & wv.x) + __popc(C.y & wv.y) + __popc(C.z & wv.z);
            rv.y = fmaxf(fmaf((float)S, inv2, fmaf(ph1, -inv, sh)), 0.0f);
            S = __popc(C.y & wv.x) + __popc(C.z & wv.y) + __popc(C.w & wv.z);
            rv.z = fmaxf(fmaf((float)S, inv2, fmaf(ph2, -inv, sh)), 0.0f);
            S = __popc(C.z & wv.x) + __popc(C.w & wv.y) + __popc(hR  & wv.z);
            rv.w = fmaxf(fmaf((float)S, inv2, fmaf(ph3, -inv, sh)), 0.0f);
            __stcs((float4*)(o2 + (size_t)o * HW), rv);
        }
    } else {
        // ---- Branch P: 1x1 conv (inv in slot 1, sh in slot 2)
        float pf0 = (float)pc0, pf1 = (float)pc1, pf2 = (float)pc2, pf3 = (float)pc3;
        float* o3 = ob + (size_t)(192 + (grp - 6) * 32) * HW;
#pragma unroll 8
        for (int o = 0; o < 32; o++) {
            uint4 wv = *(const uint4*)&sw[4 * o];
            float inv = __uint_as_float(wv.y);
            float sh  = __uint_as_float(wv.z);
            float inv2 = inv + inv;
            float4 rv;
            rv.x = fmaxf(fmaf((float)__popc(C.x & wv.x), inv2, fmaf(pf0, -inv, sh)), 0.0f);
            rv.y = fmaxf(fmaf((float)__popc(C.y & wv.x), inv2, fmaf(pf1, -inv, sh)), 0.0f);
            rv.z = fmaxf(fmaf((float)__popc(C.z & wv.x), inv2, fmaf(pf2, -inv, sh)), 0.0f);
            rv.w = fmaxf(fmaf((float)__popc(C.w & wv.x), inv2, fmaf(pf3, -inv, sh)), 0.0f);
            __stcs((float4*)(o3 + (size_t)o * HW), rv);
        }
    }
}

// ---------------------------------------------------------------------------
extern "C" void kernel_launch(void* const* d_in, const int* in_sizes, int n_in,
                              void* d_out, int out_size)
{
    const float* x = (const float*)d_in[0];
    kA<<<NPIX / 256, 256>>>(x,
                            (const float*)d_in[1], (const float*)d_in[2],
                            (const float*)d_in[3], (const float*)d_in[4],
                            (const float*)d_in[5]);
    dim3 gridB(NTHR4 / 256, 8);
    kB<<<gridB, 256>>>(
        (const float*)d_in[6],  (const float*)d_in[7],
        (const float*)d_in[8],  (const float*)d_in[9],
        (const float*)d_in[10],
        (const float*)d_in[11], (const float*)d_in[12],
        (const float*)d_in[13], (const float*)d_in[14],
        (const float*)d_in[15],
        (const float*)d_in[16], (const float*)d_in[17],
        (const float*)d_in[18], (const float*)d_in[19],
        (const float*)d_in[20],
        (float*)d_out);
}